// round 2
// baseline (speedup 1.0000x reference)
#include <cuda_runtime.h>

// Fixed problem shapes (SimpleGCN): N=50000 nodes, E=800000 edges,
// layers 256->256 (h1), 256->128 (h2), 128->128 (h3), out = [N, 512] fp32.
#define MAXN 50000
#define MAXE 800000

// ---------------- device scratch (static allocation; no cudaMalloc) --------
__device__ float g_h[(size_t)MAXN * 256];   // GEMM output buffer (max 256 cols)
__device__ float g_dinv[MAXN];              // rsqrt(deg)
__device__ int   g_cnt[MAXN];               // histogram, reused as scatter cursor
__device__ int   g_offs[MAXN + 1];          // CSR row offsets (by dst)
__device__ int   g_bsum[64];                // scan block sums
__device__ int   g_esrc[MAXE];              // CSR: src node per edge
__device__ float g_enorm[MAXE];             // CSR: dinv[src]*dinv[dst] per edge
__device__ int   g_is64;                    // edge_index dtype flag

// ---------------- dtype detection ------------------------------------------
// If edge_index is int64 (values < 2^31), every odd 32-bit word is 0.
// If int32, odd words are real random indices -> almost surely nonzero.
__global__ void k_detect(const int* __restrict__ ei32, int nwords) {
    __shared__ int any;
    if (threadIdx.x == 0) any = 0;
    __syncthreads();
    for (int i = threadIdx.x * 2 + 1; i < nwords; i += 2 * blockDim.x)
        if (ei32[i] != 0) any = 1;  // benign race
    __syncthreads();
    if (threadIdx.x == 0) g_is64 = any ? 0 : 1;
}

__device__ __forceinline__ int load_idx(const int* p32, const long long* p64,
                                        int e, int n) {
    int v = g_is64 ? (int)p64[e] : p32[e];
    // defensive clamp: wrong index -> wrong answer (diagnosable), not a trap
    v = v < 0 ? 0 : (v >= n ? n - 1 : v);
    return v;
}

// ---------------- CSR construction -----------------------------------------
__global__ void k_zero_cnt(int n) {
    int i = blockIdx.x * blockDim.x + threadIdx.x;
    if (i < n) g_cnt[i] = 0;
}

__global__ void k_count(const int* __restrict__ d32,
                        const long long* __restrict__ d64, int E, int n) {
    int e = blockIdx.x * blockDim.x + threadIdx.x;
    if (e < E) atomicAdd(&g_cnt[load_idx(d32, d64, e, n)], 1);
}

__global__ void k_dinv(int n) {
    int i = blockIdx.x * blockDim.x + threadIdx.x;
    if (i < n) g_dinv[i] = rsqrtf((float)(g_cnt[i] + 1));  // +1 self-loop
}

__global__ void k_scan_local(int n) {
    __shared__ int s[1024];
    int i = blockIdx.x * 1024 + threadIdx.x;
    int v = (i < n) ? g_cnt[i] : 0;
    s[threadIdx.x] = v;
    __syncthreads();
    for (int d = 1; d < 1024; d <<= 1) {
        int t = (threadIdx.x >= (unsigned)d) ? s[threadIdx.x - d] : 0;
        __syncthreads();
        s[threadIdx.x] += t;
        __syncthreads();
    }
    if (i < n) g_offs[i] = s[threadIdx.x] - v;  // exclusive within block
    if (threadIdx.x == 1023) g_bsum[blockIdx.x] = s[1023];
}

__global__ void k_scan_bsum(int nb, int n) {
    int run = 0;
    for (int b = 0; b < nb; b++) { int t = g_bsum[b]; g_bsum[b] = run; run += t; }
    g_offs[n] = run;  // total edge count
}

__global__ void k_scan_add(int n) {
    int i = blockIdx.x * 1024 + threadIdx.x;
    if (i < n) g_offs[i] += g_bsum[blockIdx.x];
}

__global__ void k_scatter(const int* __restrict__ s32,
                          const long long* __restrict__ s64,
                          const int* __restrict__ d32,
                          const long long* __restrict__ d64, int E, int n) {
    int e = blockIdx.x * blockDim.x + threadIdx.x;
    if (e >= E) return;
    int s = load_idx(s32, s64, e, n);
    int d = load_idx(d32, d64, e, n);
    int pos = g_offs[d] + atomicAdd(&g_cnt[d], 1);
    if (pos >= 0 && pos < MAXE) {
        g_esrc[pos]  = s;
        g_enorm[pos] = g_dinv[s] * g_dinv[d];
    }
}

// ---------------- SGEMM: g_h[M,N] = A[M,K](lda) @ B[K,N] -------------------
// 64x64 tile, BK=16, 256 threads, 4x4 register tile per thread.
__global__ void k_sgemm(const float* __restrict__ A, int lda,
                        const float* __restrict__ B,
                        int M, int N, int K) {
    __shared__ float As[16][64];
    __shared__ float Bs[16][64];
    int tid = threadIdx.x;
    int tx = tid & 15, ty = tid >> 4;
    int bn = blockIdx.x * 64, bm = blockIdx.y * 64;

    int arow = tid >> 2, akq = tid & 3;          // A: 64 rows x 4 k-quads
    int brow = tid >> 4, bcol = (tid & 15) * 4;  // B: 16 k-rows x 16 col-quads

    float acc[4][4] = {};

    for (int k0 = 0; k0 < K; k0 += 16) {
        float4 av = make_float4(0.f, 0.f, 0.f, 0.f);
        int gr = bm + arow;
        if (gr < M)
            av = *(const float4*)&A[(size_t)gr * lda + k0 + akq * 4];
        As[akq * 4 + 0][arow] = av.x;
        As[akq * 4 + 1][arow] = av.y;
        As[akq * 4 + 2][arow] = av.z;
        As[akq * 4 + 3][arow] = av.w;

        float4 bv = *(const float4*)&B[(size_t)(k0 + brow) * N + bn + bcol];
        *(float4*)&Bs[brow][bcol] = bv;
        __syncthreads();

#pragma unroll
        for (int k = 0; k < 16; k++) {
            float4 a = *(const float4*)&As[k][ty * 4];
            float4 b = *(const float4*)&Bs[k][tx * 4];
            float ar[4] = {a.x, a.y, a.z, a.w};
            float br[4] = {b.x, b.y, b.z, b.w};
#pragma unroll
            for (int i = 0; i < 4; i++)
#pragma unroll
                for (int j = 0; j < 4; j++)
                    acc[i][j] += ar[i] * br[j];
        }
        __syncthreads();
    }

#pragma unroll
    for (int i = 0; i < 4; i++) {
        int gr = bm + ty * 4 + i;
        if (gr < M)
            *(float4*)&g_h[(size_t)gr * N + bn + tx * 4] =
                make_float4(acc[i][0], acc[i][1], acc[i][2], acc[i][3]);
    }
}

// ---------------- aggregation: out[d] = relu(sum_e h[src_e]*norm_e + b) ----
// One block per dst node, one thread per output column. Reads g_h (L2-resident).
template <int OC>
__global__ void k_agg(const float* __restrict__ bias,
                      float* __restrict__ out, int ldo) {
    int node = blockIdx.x;
    int col  = threadIdx.x;
    float di = g_dinv[node];
    // self-loop contribution: norm = dinv[node]^2
    float acc = g_h[(size_t)node * OC + col] * di * di;
    int beg = g_offs[node], end = g_offs[node + 1];
    for (int e = beg; e < end; e++) {
        int   s = g_esrc[e];
        float c = g_enorm[e];
        acc += g_h[(size_t)s * OC + col] * c;
    }
    out[(size_t)node * ldo + col] = fmaxf(acc + bias[col], 0.f);
}

// ---------------- host launcher ---------------------------------------------
extern "C" void kernel_launch(void* const* d_in, const int* in_sizes, int n_in,
                              void* d_out, int out_size) {
    const float* x  = (const float*)d_in[0];
    const int*       ei32 = (const int*)d_in[1];
    const long long* ei64 = (const long long*)d_in[1];
    const float* W1 = (const float*)d_in[2];
    const float* b1 = (const float*)d_in[3];
    const float* W2 = (const float*)d_in[4];
    const float* b2 = (const float*)d_in[5];
    const float* W3 = (const float*)d_in[6];
    const float* b3 = (const float*)d_in[7];
    float* out = (float*)d_out;

    int n = in_sizes[0] / 256;   // 50000
    int E = in_sizes[1] / 2;     // 800000 (element count is dtype-invariant here)

    // dtype detection: scan first 4096 32-bit words
    k_detect<<<1, 256>>>(ei32, 4096);

    const int*       s32 = ei32;
    const int*       d32 = ei32 + E;
    const long long* s64 = ei64;
    const long long* d64 = ei64 + E;

    int nb = (n + 1023) / 1024;

    // --- CSR by dst + dinv ---
    k_zero_cnt<<<(n + 255) / 256, 256>>>(n);
    k_count<<<(E + 255) / 256, 256>>>(d32, d64, E, n);
    k_dinv<<<(n + 255) / 256, 256>>>(n);
    k_scan_local<<<nb, 1024>>>(n);
    k_scan_bsum<<<1, 1>>>(nb, n);
    k_scan_add<<<nb, 1024>>>(n);
    k_zero_cnt<<<(n + 255) / 256, 256>>>(n);  // reuse g_cnt as scatter cursor
    k_scatter<<<(E + 255) / 256, 256>>>(s32, s64, d32, d64, E, n);

    // --- layer 1: 256 -> 256, output to out[:, 0:256] ---
    {
        dim3 grid(256 / 64, (n + 63) / 64);
        k_sgemm<<<grid, 256>>>(x, 256, W1, n, 256, 256);
        k_agg<256><<<n, 256>>>(b1, out, 512);
    }
    // --- layer 2: 256 -> 128, input = out[:,0:256], output to out[:,256:384] ---
    {
        dim3 grid(128 / 64, (n + 63) / 64);
        k_sgemm<<<grid, 256>>>(out, 512, W2, n, 128, 256);
        k_agg<128><<<n, 128>>>(b2, out + 256, 512);
    }
    // --- layer 3: 128 -> 128, input = out[:,256:384], output to out[:,384:512] ---
    {
        dim3 grid(128 / 64, (n + 63) / 64);
        k_sgemm<<<grid, 256>>>(out + 256, 512, W3, n, 128, 128);
        k_agg<128><<<n, 128>>>(b3, out + 384, 512);
    }
}

// round 4
// speedup vs baseline: 1.6679x; 1.6679x over previous
#include <cuda_runtime.h>
#include <cuda_bf16.h>
#include <cstdint>

// Fixed problem shapes (SimpleGCN): N=50000 nodes, E=800000 edges,
// layers 256->256 (h1), 256->128 (h2), 128->128 (h3), out = [N, 512] fp32.
#define MAXN 50000
#define MAXE 800000
#define MPAD 50048

// ---------------- device scratch (static allocation; no cudaMalloc) --------
__device__ float g_h[(size_t)MPAD * 256];   // GEMM output (max 256 cols)
__device__ float g_dinv[MAXN];
__device__ int   g_cnt[MAXN];
__device__ int   g_offs[MAXN + 1];
__device__ int   g_bsum[64];
__device__ int   g_esrc[MAXE];
__device__ float g_enorm[MAXE];
__device__ int   g_is64;

// ---------------- dtype detection -------------------------------------------
// int64 edge_index with values < 2^31 has every odd 32-bit word == 0.
__global__ void k_detect(const int* __restrict__ ei32, int nwords) {
    __shared__ int any;
    if (threadIdx.x == 0) any = 0;
    __syncthreads();
    for (int i = threadIdx.x * 2 + 1; i < nwords; i += 2 * blockDim.x)
        if (ei32[i] != 0) any = 1;
    __syncthreads();
    if (threadIdx.x == 0) g_is64 = any ? 0 : 1;
}

__device__ __forceinline__ int load_idx(const int* p32, const long long* p64,
                                        int e, int n) {
    int v = g_is64 ? (int)p64[e] : p32[e];
    v = v < 0 ? 0 : (v >= n ? n - 1 : v);
    return v;
}

// ---------------- CSR construction ------------------------------------------
__global__ void k_zero_cnt(int n) {
    int i = blockIdx.x * blockDim.x + threadIdx.x;
    if (i < n) g_cnt[i] = 0;
}
__global__ void k_count(const int* __restrict__ d32,
                        const long long* __restrict__ d64, int E, int n) {
    int e = blockIdx.x * blockDim.x + threadIdx.x;
    if (e < E) atomicAdd(&g_cnt[load_idx(d32, d64, e, n)], 1);
}
__global__ void k_dinv(int n) {
    int i = blockIdx.x * blockDim.x + threadIdx.x;
    if (i < n) g_dinv[i] = rsqrtf((float)(g_cnt[i] + 1));
}
__global__ void k_scan_local(int n) {
    __shared__ int s[1024];
    int i = blockIdx.x * 1024 + threadIdx.x;
    int v = (i < n) ? g_cnt[i] : 0;
    s[threadIdx.x] = v;
    __syncthreads();
    for (int d = 1; d < 1024; d <<= 1) {
        int t = (threadIdx.x >= (unsigned)d) ? s[threadIdx.x - d] : 0;
        __syncthreads();
        s[threadIdx.x] += t;
        __syncthreads();
    }
    if (i < n) g_offs[i] = s[threadIdx.x] - v;
    if (threadIdx.x == 1023) g_bsum[blockIdx.x] = s[1023];
}
__global__ void k_scan_bsum(int nb, int n) {
    int run = 0;
    for (int b = 0; b < nb; b++) { int t = g_bsum[b]; g_bsum[b] = run; run += t; }
    g_offs[n] = run;
}
__global__ void k_scan_add(int n) {
    int i = blockIdx.x * 1024 + threadIdx.x;
    if (i < n) g_offs[i] += g_bsum[blockIdx.x];
}
__global__ void k_scatter(const int* __restrict__ s32,
                          const long long* __restrict__ s64,
                          const int* __restrict__ d32,
                          const long long* __restrict__ d64, int E, int n) {
    int e = blockIdx.x * blockDim.x + threadIdx.x;
    if (e >= E) return;
    int s = load_idx(s32, s64, e, n);
    int d = load_idx(d32, d64, e, n);
    int pos = g_offs[d] + atomicAdd(&g_cnt[d], 1);
    if (pos >= 0 && pos < MAXE) {
        g_esrc[pos]  = s;
        g_enorm[pos] = g_dinv[s] * g_dinv[d];
    }
}

// ---------------- warp-MMA bf16-split GEMM ----------------------------------
// C[M,N] = A[M,K] @ W[K,N], fp32 in/out, 3-term bf16 split on tensor cores.
// CTA tile 128x128, 8 warps (2M x 4N), warp tile 64x32 via m16n8k16.
// K staged 32 at a time; fp32->bf16 hi/lo conversion fused into staging.

#define ROWW 20   // smem row stride in 32-bit words (40 bf16 = 80B, conflict-free)

__device__ __forceinline__ void mma_bf16(float* c, uint32_t a0, uint32_t a1,
                                         uint32_t a2, uint32_t a3,
                                         uint32_t b0, uint32_t b1) {
    asm volatile(
        "mma.sync.aligned.m16n8k16.row.col.f32.bf16.bf16.f32 "
        "{%0,%1,%2,%3}, {%4,%5,%6,%7}, {%8,%9}, {%0,%1,%2,%3};"
        : "+f"(c[0]), "+f"(c[1]), "+f"(c[2]), "+f"(c[3])
        : "r"(a0), "r"(a1), "r"(a2), "r"(a3), "r"(b0), "r"(b1));
}

// convert 16 fp32 -> bf16 hi/lo, store 16-elem rows as 2x uint4 each
__device__ __forceinline__ void cvt_store16(uint32_t* sh, uint32_t* sl,
                                            int wordbase, const float* v) {
    uint32_t ph[8], pl[8];
#pragma unroll
    for (int i = 0; i < 8; i++) {
        __nv_bfloat16 h0 = __float2bfloat16(v[2 * i]);
        __nv_bfloat16 h1 = __float2bfloat16(v[2 * i + 1]);
        __nv_bfloat16 l0 = __float2bfloat16(v[2 * i] - __bfloat162float(h0));
        __nv_bfloat16 l1 = __float2bfloat16(v[2 * i + 1] - __bfloat162float(h1));
        ph[i] = (uint32_t)*(uint16_t*)&h0 | ((uint32_t)*(uint16_t*)&h1 << 16);
        pl[i] = (uint32_t)*(uint16_t*)&l0 | ((uint32_t)*(uint16_t*)&l1 << 16);
    }
    *(uint4*)&sh[wordbase]     = make_uint4(ph[0], ph[1], ph[2], ph[3]);
    *(uint4*)&sh[wordbase + 4] = make_uint4(ph[4], ph[5], ph[6], ph[7]);
    *(uint4*)&sl[wordbase]     = make_uint4(pl[0], pl[1], pl[2], pl[3]);
    *(uint4*)&sl[wordbase + 4] = make_uint4(pl[4], pl[5], pl[6], pl[7]);
}

__global__ void __launch_bounds__(256)
k_gemm_mma(const float* __restrict__ A, int lda,
           const float* __restrict__ W, int N,
           int M, int K) {
    __shared__ uint32_t sAh[128 * ROWW], sAl[128 * ROWW];
    __shared__ uint32_t sBh[128 * ROWW], sBl[128 * ROWW];

    const int tid  = threadIdx.x;
    const int lane = tid & 31;
    const int wid  = tid >> 5;
    const int wm   = wid & 1;          // M warp (64 rows)
    const int wn   = wid >> 1;         // N warp (32 cols)
    const int bm   = blockIdx.x * 128;
    const int bn   = blockIdx.y * 128;

    const int l4 = lane >> 2;
    const int l2 = (lane & 3) * 2;

    float acc[4][4][4];
#pragma unroll
    for (int i = 0; i < 4; i++)
#pragma unroll
        for (int j = 0; j < 4; j++)
#pragma unroll
            for (int k = 0; k < 4; k++) acc[i][j][k] = 0.f;

    // staging roles
    const int ar = tid & 127, ah = tid >> 7;   // A: row, k-half(16)
    const int nr = tid & 127, kg = tid >> 7;   // B: n, k-half(16)

    const int nStages = K >> 5;
    for (int st = 0; st < nStages; st++) {
        const int k0 = st << 5;
        __syncthreads();
        // stage A [128 x 32] fp32 -> hi/lo bf16, smem layout [m][k]
        {
            float v[16];
            const int grow = bm + ar;
            if (grow < M) {
                const float* p = &A[(size_t)grow * lda + k0 + ah * 16];
#pragma unroll
                for (int q = 0; q < 4; q++) {
                    float4 f = *(const float4*)&p[q * 4];
                    v[q * 4 + 0] = f.x; v[q * 4 + 1] = f.y;
                    v[q * 4 + 2] = f.z; v[q * 4 + 3] = f.w;
                }
            } else {
#pragma unroll
                for (int q = 0; q < 16; q++) v[q] = 0.f;
            }
            cvt_store16(sAh, sAl, ar * ROWW + ah * 8, v);
        }
        // stage B [128 n x 32 k] from W[K,N]: smem layout [n][k] (transpose)
        {
            float v[16];
#pragma unroll
            for (int kk = 0; kk < 16; kk++)
                v[kk] = W[(size_t)(k0 + kg * 16 + kk) * N + bn + nr];
            cvt_store16(sBh, sBl, nr * ROWW + kg * 8, v);
        }
        __syncthreads();

#pragma unroll
        for (int ks = 0; ks < 2; ks++) {
            const int kwb = ks * 8 + (lane & 3);  // word offset of this lane's k-pair
            uint32_t bh[4][2], bl[4][2];
#pragma unroll
            for (int nt = 0; nt < 4; nt++) {
                int rw = (wn * 32 + nt * 8 + l4) * ROWW + kwb;
                bh[nt][0] = sBh[rw];     bh[nt][1] = sBh[rw + 4];
                bl[nt][0] = sBl[rw];     bl[nt][1] = sBl[rw + 4];
            }
#pragma unroll
            for (int mt = 0; mt < 4; mt++) {
                int r0 = (wm * 64 + mt * 16 + l4) * ROWW + kwb;
                int r1 = r0 + 8 * ROWW;
                uint32_t ah0 = sAh[r0], ah1 = sAh[r1];
                uint32_t ah2 = sAh[r0 + 4], ah3 = sAh[r1 + 4];
                uint32_t al0 = sAl[r0], al1 = sAl[r1];
                uint32_t al2 = sAl[r0 + 4], al3 = sAl[r1 + 4];
#pragma unroll
                for (int nt = 0; nt < 4; nt++) {
                    mma_bf16(acc[mt][nt], ah0, ah1, ah2, ah3, bh[nt][0], bh[nt][1]);
                    mma_bf16(acc[mt][nt], ah0, ah1, ah2, ah3, bl[nt][0], bl[nt][1]);
                    mma_bf16(acc[mt][nt], al0, al1, al2, al3, bh[nt][0], bh[nt][1]);
                }
            }
        }
    }

    // epilogue: write fp32 to g_h[M, N] (32B-sector aligned float2 stores)
#pragma unroll
    for (int mt = 0; mt < 4; mt++) {
#pragma unroll
        for (int nt = 0; nt < 4; nt++) {
            int row = bm + wm * 64 + mt * 16 + l4;
            int col = bn + wn * 32 + nt * 8 + l2;
            if (row < M)
                *(float2*)&g_h[(size_t)row * N + col] =
                    make_float2(acc[mt][nt][0], acc[mt][nt][1]);
            if (row + 8 < M)
                *(float2*)&g_h[(size_t)(row + 8) * N + col] =
                    make_float2(acc[mt][nt][2], acc[mt][nt][3]);
        }
    }
}

// ---------------- aggregation: out[d] = relu(sum h[src]*norm + self + b) ----
template <int OC>
__global__ void k_agg(const float* __restrict__ bias,
                      float* __restrict__ out, int ldo) {
    int node = blockIdx.x;
    int c4   = threadIdx.x;                 // OC/4 threads
    float di = g_dinv[node];
    float s2 = di * di;
    float4 h0 = *(const float4*)&g_h[(size_t)node * OC + c4 * 4];
    float4 acc = make_float4(h0.x * s2, h0.y * s2, h0.z * s2, h0.w * s2);
    int beg = g_offs[node], end = g_offs[node + 1];
    for (int e = beg; e < end; e++) {
        int   s = g_esrc[e];
        float w = g_enorm[e];
        float4 hv = *(const float4*)&g_h[(size_t)s * OC + c4 * 4];
        acc.x += hv.x * w; acc.y += hv.y * w;
        acc.z += hv.z * w; acc.w += hv.w * w;
    }
    float4 b = *(const float4*)&bias[c4 * 4];
    float4 r;
    r.x = fmaxf(acc.x + b.x, 0.f);
    r.y = fmaxf(acc.y + b.y, 0.f);
    r.z = fmaxf(acc.z + b.z, 0.f);
    r.w = fmaxf(acc.w + b.w, 0.f);
    *(float4*)&out[(size_t)node * ldo + c4 * 4] = r;
}

// ---------------- host launcher ----------------------------------------------
extern "C" void kernel_launch(void* const* d_in, const int* in_sizes, int n_in,
                              void* d_out, int out_size) {
    const float* x  = (const float*)d_in[0];
    const int*       ei32 = (const int*)d_in[1];
    const long long* ei64 = (const long long*)d_in[1];
    const float* W1 = (const float*)d_in[2];
    const float* b1 = (const float*)d_in[3];
    const float* W2 = (const float*)d_in[4];
    const float* b2 = (const float*)d_in[5];
    const float* W3 = (const float*)d_in[6];
    const float* b3 = (const float*)d_in[7];
    float* out = (float*)d_out;

    int n = in_sizes[0] / 256;   // 50000
    int E = in_sizes[1] / 2;     // 800000

    k_detect<<<1, 256>>>(ei32, 4096);

    const int*       s32 = ei32;
    const int*       d32 = ei32 + E;
    const long long* s64 = ei64;
    const long long* d64 = ei64 + E;

    int nb = (n + 1023) / 1024;
    k_zero_cnt<<<(n + 255) / 256, 256>>>(n);
    k_count<<<(E + 255) / 256, 256>>>(d32, d64, E, n);
    k_dinv<<<(n + 255) / 256, 256>>>(n);
    k_scan_local<<<nb, 1024>>>(n);
    k_scan_bsum<<<1, 1>>>(nb, n);
    k_scan_add<<<nb, 1024>>>(n);
    k_zero_cnt<<<(n + 255) / 256, 256>>>(n);
    k_scatter<<<(E + 255) / 256, 256>>>(s32, s64, d32, d64, E, n);

    const int mtiles = (n + 127) / 128;  // 391

    // --- layer 1: 256 -> 256 ---
    k_gemm_mma<<<dim3(mtiles, 2), 256>>>(x, 256, W1, 256, n, 256);
    k_agg<256><<<n, 64>>>(b1, out, 512);

    // --- layer 2: 256 -> 128 (input = out[:,0:256]) ---
    k_gemm_mma<<<dim3(mtiles, 1), 256>>>(out, 512, W2, 128, n, 256);
    k_agg<128><<<n, 32>>>(b2, out + 256, 512);

    // --- layer 3: 128 -> 128 (input = out[:,256:384]) ---
    k_gemm_mma<<<dim3(mtiles, 1), 256>>>(out + 256, 512, W3, 128, n, 128);
    k_agg<128><<<n, 32>>>(b3, out + 384, 512);
}